// round 1
// baseline (speedup 1.0000x reference)
#include <cuda_runtime.h>

// ---------------------------------------------------------------------------
// KQEnergyBlock: B=8, N=1024, D=768, H=12, Z=64, HID=3072
//
// Decomposition (verified algebraically against the JAX reference):
//   Q = x @ Wq^T                         (M=8192, 768, 768)
//   K = x @ Wk^T
//   S[b,h]   = beta_h * Q_h @ K_h^T      (per (b,h): 1024x1024, k=64)
//   P        = softmax(S, axis=-1)
//   AV1[b,h] = P   @ K_h                 (1024x64, k=1024)
//   AV2[b,h] = P^T @ Q_h
//   out  = AV1_flat @ Wq  (no transpose: Wq viewed as (H*Z, D))
//   out += AV2_flat @ Wk
//   hid  = relu(x @ Wmlp^T)              (8192 x 3072)
//   out += hid @ Wmlp
// ---------------------------------------------------------------------------

namespace {
constexpr int Bc = 8, Nc = 1024, Dc = 768, Hc = 12, Zc = 64, HIDc = 3072;
constexpr int Mrows = Bc * Nc;  // 8192
}

// Scratch (device globals: allocation-free per harness rules)
__device__ float g_Q[Mrows * Dc];
__device__ float g_K[Mrows * Dc];
__device__ float g_AV1[Mrows * Dc];
__device__ float g_AV2[Mrows * Dc];
__device__ float g_attn[(size_t)Bc * Hc * Nc * Nc];   // 402 MB
__device__ float g_hid[(size_t)Mrows * HIDc];         // 100 MB

enum { EPI_STORE = 0, EPI_SCALE = 1, EPI_RELU = 2, EPI_ADD = 3 };

// Generic batched tiled SGEMM.
//  A logical MxK:  TA=0 -> A[m*lda+k],  TA=1 -> A[k*lda+m]
//  B logical KxN:  TB=0 -> B[k*ldb+n],  TB=1 -> B[n*ldb+k]
//  batch z = bi*Hdiv + hi with independent (b, h) strides per operand.
template <int BM, int BN, int BK, int TM, int TN, int TA, int TB, int EPI>
__global__ __launch_bounds__((BM / TM) * (BN / TN))
void gemm_k(const float* __restrict__ Abase, const float* __restrict__ Bbase,
            float* __restrict__ Cbase,
            int M, int N, int K, int lda, int ldb, int ldc,
            long sAb, long sAh, long sBb, long sBh, long sCb, long sCh,
            int Hdiv, const float* __restrict__ betas)
{
    constexpr int NTHREADS = (BM / TM) * (BN / TN);
    __shared__ float As[BK][BM + 4];
    __shared__ float Bs[BK][BN + 4];

    const int bz = blockIdx.z;
    const int bi = bz / Hdiv;
    const int hi = bz % Hdiv;
    const float* A = Abase + bi * sAb + hi * sAh;
    const float* Bm = Bbase + bi * sBb + hi * sBh;
    float* C = Cbase + bi * sCb + hi * sCh;

    const int t  = threadIdx.x;
    const int tc = t % (BN / TN);
    const int tr = t / (BN / TN);
    const int m0 = blockIdx.y * BM;
    const int n0 = blockIdx.x * BN;

    float acc[TM][TN];
#pragma unroll
    for (int i = 0; i < TM; i++)
#pragma unroll
        for (int j = 0; j < TN; j++) acc[i][j] = 0.f;

    for (int k0 = 0; k0 < K; k0 += BK) {
        // ---- load A tile into As[k][m] ----
        if (TA == 0) {
#pragma unroll
            for (int it = 0; it < (BM * BK) / NTHREADS; ++it) {
                int idx = t + it * NTHREADS;
                int m = idx / BK, k = idx % BK;
                int gm = m0 + m, gk = k0 + k;
                As[k][m] = (gm < M && gk < K) ? A[(long)gm * lda + gk] : 0.f;
            }
        } else {
#pragma unroll
            for (int it = 0; it < (BM * BK) / NTHREADS; ++it) {
                int idx = t + it * NTHREADS;
                int k = idx / BM, m = idx % BM;
                int gm = m0 + m, gk = k0 + k;
                As[k][m] = (gm < M && gk < K) ? A[(long)gk * lda + gm] : 0.f;
            }
        }
        // ---- load B tile into Bs[k][n] ----
        if (TB == 0) {
#pragma unroll
            for (int it = 0; it < (BK * BN) / NTHREADS; ++it) {
                int idx = t + it * NTHREADS;
                int k = idx / BN, n = idx % BN;
                int gn = n0 + n, gk = k0 + k;
                Bs[k][n] = (gn < N && gk < K) ? Bm[(long)gk * ldb + gn] : 0.f;
            }
        } else {
#pragma unroll
            for (int it = 0; it < (BK * BN) / NTHREADS; ++it) {
                int idx = t + it * NTHREADS;
                int n = idx / BK, k = idx % BK;
                int gn = n0 + n, gk = k0 + k;
                Bs[k][n] = (gn < N && gk < K) ? Bm[(long)gn * ldb + gk] : 0.f;
            }
        }
        __syncthreads();

#pragma unroll
        for (int kk = 0; kk < BK; kk++) {
            float a[TM], b[TN];
#pragma unroll
            for (int i = 0; i < TM; i += 4) {
                float4 v = *reinterpret_cast<const float4*>(&As[kk][tr * TM + i]);
                a[i] = v.x; a[i + 1] = v.y; a[i + 2] = v.z; a[i + 3] = v.w;
            }
#pragma unroll
            for (int j = 0; j < TN; j += 4) {
                float4 v = *reinterpret_cast<const float4*>(&Bs[kk][tc * TN + j]);
                b[j] = v.x; b[j + 1] = v.y; b[j + 2] = v.z; b[j + 3] = v.w;
            }
#pragma unroll
            for (int i = 0; i < TM; i++)
#pragma unroll
                for (int j = 0; j < TN; j++) acc[i][j] += a[i] * b[j];
        }
        __syncthreads();
    }

    float scale = 1.f;
    if (EPI == EPI_SCALE) scale = betas[hi];

#pragma unroll
    for (int i = 0; i < TM; i++) {
        int gm = m0 + tr * TM + i;
        if (gm >= M) continue;
#pragma unroll
        for (int j = 0; j < TN; j++) {
            int gn = n0 + tc * TN + j;
            if (gn >= N) continue;
            float v = acc[i][j];
            if (EPI == EPI_SCALE) v *= scale;
            if (EPI == EPI_RELU) v = fmaxf(v, 0.f);
            long off = (long)gm * ldc + gn;
            if (EPI == EPI_ADD) C[off] += v;
            else                C[off] = v;
        }
    }
}

// Row softmax over 1024 columns; one 256-thread block per row.
__global__ __launch_bounds__(256) void softmax_k(float* __restrict__ a)
{
    const long row = blockIdx.x;
    float* p = a + row * (long)Nc;
    const int t = threadIdx.x;

    float v[4];
    float m = -1e30f;
#pragma unroll
    for (int i = 0; i < 4; i++) {
        v[i] = p[t + i * 256];
        m = fmaxf(m, v[i]);
    }
    __shared__ float red[256];
    red[t] = m;
    __syncthreads();
#pragma unroll
    for (int s = 128; s > 0; s >>= 1) {
        if (t < s) red[t] = fmaxf(red[t], red[t + s]);
        __syncthreads();
    }
    m = red[0];
    __syncthreads();

    float sum = 0.f;
#pragma unroll
    for (int i = 0; i < 4; i++) {
        v[i] = __expf(v[i] - m);
        sum += v[i];
    }
    red[t] = sum;
    __syncthreads();
#pragma unroll
    for (int s = 128; s > 0; s >>= 1) {
        if (t < s) red[t] += red[t + s];
        __syncthreads();
    }
    const float inv = 1.f / red[0];
#pragma unroll
    for (int i = 0; i < 4; i++) p[t + i * 256] = v[i] * inv;
}

template <int BM, int BN, int BK, int TM, int TN, int TA, int TB, int EPI>
static void run_gemm(const float* A, const float* B, float* C,
                     int M, int N, int K, int lda, int ldb, int ldc,
                     long sAb, long sAh, long sBb, long sBh, long sCb, long sCh,
                     int batches, int Hdiv, const float* betas)
{
    dim3 grid((N + BN - 1) / BN, (M + BM - 1) / BM, batches);
    gemm_k<BM, BN, BK, TM, TN, TA, TB, EPI>
        <<<grid, (BM / TM) * (BN / TN)>>>(A, B, C, M, N, K, lda, ldb, ldc,
                                          sAb, sAh, sBb, sBh, sCb, sCh,
                                          Hdiv, betas);
}

extern "C" void kernel_launch(void* const* d_in, const int* in_sizes, int n_in,
                              void* d_out, int out_size)
{
    const float* x     = (const float*)d_in[0];
    const float* Wq    = (const float*)d_in[1];
    const float* Wk    = (const float*)d_in[2];
    const float* betas = (const float*)d_in[3];
    const float* Wmlp  = (const float*)d_in[4];
    float* out = (float*)d_out;

    float *Q, *K, *AV1, *AV2, *attn, *hid;
    cudaGetSymbolAddress((void**)&Q,    g_Q);
    cudaGetSymbolAddress((void**)&K,    g_K);
    cudaGetSymbolAddress((void**)&AV1,  g_AV1);
    cudaGetSymbolAddress((void**)&AV2,  g_AV2);
    cudaGetSymbolAddress((void**)&attn, g_attn);
    cudaGetSymbolAddress((void**)&hid,  g_hid);

    const long ND = (long)Nc * Dc;          // per-batch stride in Q/K/AV buffers
    const long NN = (long)Nc * Nc;          // per-head stride in attn

    // 1) Q = x @ Wq^T ; K = x @ Wk^T
    run_gemm<128, 128, 16, 8, 8, 0, 1, EPI_STORE>(
        x, Wq, Q, Mrows, Dc, Dc, Dc, Dc, Dc, 0, 0, 0, 0, 0, 0, 1, 1, nullptr);
    run_gemm<128, 128, 16, 8, 8, 0, 1, EPI_STORE>(
        x, Wk, K, Mrows, Dc, Dc, Dc, Dc, Dc, 0, 0, 0, 0, 0, 0, 1, 1, nullptr);

    // 2) S[b,h] = beta_h * Q_h @ K_h^T   (batched over 96 (b,h) pairs)
    run_gemm<128, 128, 16, 8, 8, 0, 1, EPI_SCALE>(
        Q, K, attn, Nc, Nc, Zc, Dc, Dc, Nc,
        ND, Zc, ND, Zc, (long)Hc * NN, NN, Bc * Hc, Hc, betas);

    // 3) row softmax
    softmax_k<<<Bc * Hc * Nc, 256>>>(attn);

    // 4) AV1 = P @ K_h ; AV2 = P^T @ Q_h
    run_gemm<128, 64, 16, 8, 4, 0, 0, EPI_STORE>(
        attn, K, AV1, Nc, Zc, Nc, Nc, Dc, Dc,
        (long)Hc * NN, NN, ND, Zc, ND, Zc, Bc * Hc, Hc, nullptr);
    run_gemm<128, 64, 16, 8, 4, 1, 0, EPI_STORE>(
        attn, Q, AV2, Nc, Zc, Nc, Nc, Dc, Dc,
        (long)Hc * NN, NN, ND, Zc, ND, Zc, Bc * Hc, Hc, nullptr);

    // 5) out = AV1 @ Wq ; out += AV2 @ Wk
    run_gemm<128, 128, 16, 8, 8, 0, 0, EPI_STORE>(
        AV1, Wq, out, Mrows, Dc, Dc, Dc, Dc, Dc, 0, 0, 0, 0, 0, 0, 1, 1, nullptr);
    run_gemm<128, 128, 16, 8, 8, 0, 0, EPI_ADD>(
        AV2, Wk, out, Mrows, Dc, Dc, Dc, Dc, Dc, 0, 0, 0, 0, 0, 0, 1, 1, nullptr);

    // 6) hid = relu(x @ Wmlp^T) ; out += hid @ Wmlp
    run_gemm<128, 128, 16, 8, 8, 0, 1, EPI_RELU>(
        x, Wmlp, hid, Mrows, HIDc, Dc, Dc, Dc, HIDc, 0, 0, 0, 0, 0, 0, 1, 1, nullptr);
    run_gemm<128, 128, 16, 8, 8, 0, 0, EPI_ADD>(
        hid, Wmlp, out, Mrows, Dc, HIDc, HIDc, Dc, Dc, 0, 0, 0, 0, 0, 0, 1, 1, nullptr);
}

// round 2
// speedup vs baseline: 2.7579x; 2.7579x over previous
#include <cuda_runtime.h>
#include <cstdint>

// ---------------------------------------------------------------------------
// KQEnergyBlock: B=8, N=1024, D=768, H=12, Z=64, HID=3072
// Decomposition:
//   Q = x @ Wq^T ; K = x @ Wk^T
//   S[b,h] = beta_h * Q_h @ K_h^T ; P = softmax(S)
//   AV1 = P @ K_h ; AV2 = P^T @ Q_h
//   out = AV1@Wq + AV2@Wk + relu(x@Wmlp^T)@Wmlp
// All GEMMs on tensor cores via tf32 mma.sync.m16n8k8.
// ---------------------------------------------------------------------------

namespace {
constexpr int Bc = 8, Nc = 1024, Dc = 768, Hc = 12, Zc = 64, HIDc = 3072;
constexpr int Mrows = Bc * Nc;  // 8192
}

__device__ float g_Q[Mrows * Dc];
__device__ float g_K[Mrows * Dc];
__device__ float g_AV1[Mrows * Dc];
__device__ float g_AV2[Mrows * Dc];
__device__ float g_attn[(size_t)Bc * Hc * Nc * Nc];   // 402 MB
__device__ float g_hid[(size_t)Mrows * HIDc];         // 100 MB

enum { EPI_STORE = 0, EPI_SCALE = 1, EPI_RELU = 2, EPI_ADD = 3 };

__device__ __forceinline__ uint32_t f2tf32(float f) {
    uint32_t r;
    asm("cvt.rna.tf32.f32 %0, %1;" : "=r"(r) : "f"(f));
    return r;
}

__device__ __forceinline__ void mma_tf32(float c[4],
                                         uint32_t a0, uint32_t a1, uint32_t a2, uint32_t a3,
                                         uint32_t b0, uint32_t b1) {
    asm volatile(
        "mma.sync.aligned.m16n8k8.row.col.f32.tf32.tf32.f32 "
        "{%0,%1,%2,%3}, {%4,%5,%6,%7}, {%8,%9}, {%0,%1,%2,%3};\n"
        : "+f"(c[0]), "+f"(c[1]), "+f"(c[2]), "+f"(c[3])
        : "r"(a0), "r"(a1), "r"(a2), "r"(a3), "r"(b0), "r"(b1));
}

// Generic batched tf32 tensor-core GEMM. Dims must divide tiles exactly.
//  A logical MxK:  TA=0 -> A[m*lda+k],  TA=1 -> A[k*lda+m]
//  B logical KxN:  TB=0 -> B[k*ldb+n],  TB=1 -> B[n*ldb+k]
template <int BM, int BN, int BK, int WM, int WN, int TA, int TB, int EPI>
__global__ __launch_bounds__((BM / WM) * (BN / WN) * 32)
void gemm_mma(const float* __restrict__ Abase, const float* __restrict__ Bbase,
              float* __restrict__ Cbase,
              int M, int N, int K, int lda, int ldb, int ldc,
              long sAb, long sAh, long sBb, long sBh, long sCb, long sCh,
              int Hdiv, const float* __restrict__ betas)
{
    constexpr int NWARPS = (BM / WM) * (BN / WN);
    constexpr int NT = NWARPS * 32;
    constexpr int PAD = 4;
    constexpr int MT = WM / 16;   // m16 tiles per warp
    constexpr int NTI = WN / 8;   // n8 tiles per warp

    __shared__ uint32_t As[BK][BM + PAD];
    __shared__ uint32_t Bs[BK][BN + PAD];

    const int bz = blockIdx.z;
    const int bi = bz / Hdiv;
    const int hi = bz % Hdiv;
    const float* A = Abase + bi * sAb + hi * sAh;
    const float* Bm = Bbase + bi * sBb + hi * sBh;
    float* C = Cbase + bi * sCb + hi * sCh;

    const int t = threadIdx.x;
    const int warp = t >> 5;
    const int lane = t & 31;
    const int group = lane >> 2;   // 0..7
    const int tg = lane & 3;       // 0..3
    const int wm = warp / (BN / WN);
    const int wn = warp % (BN / WN);
    const int m0 = blockIdx.y * BM;
    const int n0 = blockIdx.x * BN;

    float acc[MT][NTI][4];
#pragma unroll
    for (int i = 0; i < MT; i++)
#pragma unroll
        for (int j = 0; j < NTI; j++)
#pragma unroll
            for (int r = 0; r < 4; r++) acc[i][j][r] = 0.f;

    for (int k0 = 0; k0 < K; k0 += BK) {
        // ---- A tile -> As[k][m] ----
        if (TA == 0) {
#pragma unroll
            for (int it = 0; it < (BM * BK / 4) / NT; ++it) {
                int idx = t + it * NT;
                int m = idx / (BK / 4);
                int q = idx % (BK / 4);
                float4 v = *reinterpret_cast<const float4*>(
                    &A[(long)(m0 + m) * lda + k0 + q * 4]);
                As[q * 4 + 0][m] = f2tf32(v.x);
                As[q * 4 + 1][m] = f2tf32(v.y);
                As[q * 4 + 2][m] = f2tf32(v.z);
                As[q * 4 + 3][m] = f2tf32(v.w);
            }
        } else {
#pragma unroll
            for (int it = 0; it < (BM * BK / 4) / NT; ++it) {
                int idx = t + it * NT;
                int mq = idx % (BM / 4);
                int k = idx / (BM / 4);
                float4 v = *reinterpret_cast<const float4*>(
                    &A[(long)(k0 + k) * lda + m0 + mq * 4]);
                As[k][mq * 4 + 0] = f2tf32(v.x);
                As[k][mq * 4 + 1] = f2tf32(v.y);
                As[k][mq * 4 + 2] = f2tf32(v.z);
                As[k][mq * 4 + 3] = f2tf32(v.w);
            }
        }
        // ---- B tile -> Bs[k][n] ----
        if (TB == 0) {
#pragma unroll
            for (int it = 0; it < (BK * BN / 4) / NT; ++it) {
                int idx = t + it * NT;
                int nq = idx % (BN / 4);
                int k = idx / (BN / 4);
                float4 v = *reinterpret_cast<const float4*>(
                    &Bm[(long)(k0 + k) * ldb + n0 + nq * 4]);
                Bs[k][nq * 4 + 0] = f2tf32(v.x);
                Bs[k][nq * 4 + 1] = f2tf32(v.y);
                Bs[k][nq * 4 + 2] = f2tf32(v.z);
                Bs[k][nq * 4 + 3] = f2tf32(v.w);
            }
        } else {
#pragma unroll
            for (int it = 0; it < (BK * BN / 4) / NT; ++it) {
                int idx = t + it * NT;
                int n = idx / (BK / 4);
                int q = idx % (BK / 4);
                float4 v = *reinterpret_cast<const float4*>(
                    &Bm[(long)(n0 + n) * ldb + k0 + q * 4]);
                Bs[q * 4 + 0][n] = f2tf32(v.x);
                Bs[q * 4 + 1][n] = f2tf32(v.y);
                Bs[q * 4 + 2][n] = f2tf32(v.z);
                Bs[q * 4 + 3][n] = f2tf32(v.w);
            }
        }
        __syncthreads();

#pragma unroll
        for (int kk = 0; kk < BK; kk += 8) {
            uint32_t af[MT][4], bf[NTI][2];
#pragma unroll
            for (int mt = 0; mt < MT; mt++) {
                int mrow = wm * WM + mt * 16 + group;
                af[mt][0] = As[kk + tg][mrow];
                af[mt][1] = As[kk + tg][mrow + 8];
                af[mt][2] = As[kk + tg + 4][mrow];
                af[mt][3] = As[kk + tg + 4][mrow + 8];
            }
#pragma unroll
            for (int nt = 0; nt < NTI; nt++) {
                int ncol = wn * WN + nt * 8 + group;
                bf[nt][0] = Bs[kk + tg][ncol];
                bf[nt][1] = Bs[kk + tg + 4][ncol];
            }
#pragma unroll
            for (int mt = 0; mt < MT; mt++)
#pragma unroll
                for (int nt = 0; nt < NTI; nt++)
                    mma_tf32(acc[mt][nt], af[mt][0], af[mt][1], af[mt][2], af[mt][3],
                             bf[nt][0], bf[nt][1]);
        }
        __syncthreads();
    }

    float scale = 1.f;
    if (EPI == EPI_SCALE) scale = betas[hi];

#pragma unroll
    for (int mt = 0; mt < MT; mt++) {
#pragma unroll
        for (int nt = 0; nt < NTI; nt++) {
            int gm = m0 + wm * WM + mt * 16 + group;
            int gn = n0 + wn * WN + nt * 8 + tg * 2;
#pragma unroll
            for (int half = 0; half < 2; half++) {
                int row = gm + half * 8;
                float v0 = acc[mt][nt][half * 2 + 0];
                float v1 = acc[mt][nt][half * 2 + 1];
                if (EPI == EPI_SCALE) { v0 *= scale; v1 *= scale; }
                if (EPI == EPI_RELU)  { v0 = fmaxf(v0, 0.f); v1 = fmaxf(v1, 0.f); }
                float2* p = reinterpret_cast<float2*>(&C[(long)row * ldc + gn]);
                if (EPI == EPI_ADD) {
                    float2 old = *p;
                    p->x = old.x + v0;
                    p->y = old.y + v1;
                } else {
                    float2 w; w.x = v0; w.y = v1;
                    *p = w;
                }
            }
        }
    }
}

// Row softmax over 1024 columns; one 256-thread block per row.
__global__ __launch_bounds__(256) void softmax_k(float* __restrict__ a)
{
    const long row = blockIdx.x;
    float* p = a + row * (long)Nc;
    const int t = threadIdx.x;

    float v[4];
    float m = -1e30f;
#pragma unroll
    for (int i = 0; i < 4; i++) {
        v[i] = p[t + i * 256];
        m = fmaxf(m, v[i]);
    }
    __shared__ float red[256];
    red[t] = m;
    __syncthreads();
#pragma unroll
    for (int s = 128; s > 0; s >>= 1) {
        if (t < s) red[t] = fmaxf(red[t], red[t + s]);
        __syncthreads();
    }
    m = red[0];
    __syncthreads();

    float sum = 0.f;
#pragma unroll
    for (int i = 0; i < 4; i++) {
        v[i] = __expf(v[i] - m);
        sum += v[i];
    }
    red[t] = sum;
    __syncthreads();
#pragma unroll
    for (int s = 128; s > 0; s >>= 1) {
        if (t < s) red[t] += red[t + s];
        __syncthreads();
    }
    const float inv = 1.f / red[0];
#pragma unroll
    for (int i = 0; i < 4; i++) p[t + i * 256] = v[i] * inv;
}

template <int BM, int BN, int BK, int WM, int WN, int TA, int TB, int EPI>
static void run_gemm(const float* A, const float* B, float* C,
                     int M, int N, int K, int lda, int ldb, int ldc,
                     long sAb, long sAh, long sBb, long sBh, long sCb, long sCh,
                     int batches, int Hdiv, const float* betas)
{
    dim3 grid(N / BN, M / BM, batches);
    gemm_mma<BM, BN, BK, WM, WN, TA, TB, EPI>
        <<<grid, (BM / WM) * (BN / WN) * 32>>>(A, B, C, M, N, K, lda, ldb, ldc,
                                               sAb, sAh, sBb, sBh, sCb, sCh,
                                               Hdiv, betas);
}

extern "C" void kernel_launch(void* const* d_in, const int* in_sizes, int n_in,
                              void* d_out, int out_size)
{
    const float* x     = (const float*)d_in[0];
    const float* Wq    = (const float*)d_in[1];
    const float* Wk    = (const float*)d_in[2];
    const float* betas = (const float*)d_in[3];
    const float* Wmlp  = (const float*)d_in[4];
    float* out = (float*)d_out;

    float *Q, *K, *AV1, *AV2, *attn, *hid;
    cudaGetSymbolAddress((void**)&Q,    g_Q);
    cudaGetSymbolAddress((void**)&K,    g_K);
    cudaGetSymbolAddress((void**)&AV1,  g_AV1);
    cudaGetSymbolAddress((void**)&AV2,  g_AV2);
    cudaGetSymbolAddress((void**)&attn, g_attn);
    cudaGetSymbolAddress((void**)&hid,  g_hid);

    const long ND = (long)Nc * Dc;
    const long NN = (long)Nc * Nc;

    // 1) Q = x @ Wq^T ; K = x @ Wk^T
    run_gemm<128, 128, 16, 64, 32, 0, 1, EPI_STORE>(
        x, Wq, Q, Mrows, Dc, Dc, Dc, Dc, Dc, 0, 0, 0, 0, 0, 0, 1, 1, nullptr);
    run_gemm<128, 128, 16, 64, 32, 0, 1, EPI_STORE>(
        x, Wk, K, Mrows, Dc, Dc, Dc, Dc, Dc, 0, 0, 0, 0, 0, 0, 1, 1, nullptr);

    // 2) S[b,h] = beta_h * Q_h @ K_h^T
    run_gemm<128, 128, 16, 64, 32, 0, 1, EPI_SCALE>(
        Q, K, attn, Nc, Nc, Zc, Dc, Dc, Nc,
        ND, Zc, ND, Zc, (long)Hc * NN, NN, Bc * Hc, Hc, betas);

    // 3) row softmax
    softmax_k<<<Bc * Hc * Nc, 256>>>(attn);

    // 4) AV1 = P @ K_h ; AV2 = P^T @ Q_h
    run_gemm<128, 64, 16, 64, 32, 0, 0, EPI_STORE>(
        attn, K, AV1, Nc, Zc, Nc, Nc, Dc, Dc,
        (long)Hc * NN, NN, ND, Zc, ND, Zc, Bc * Hc, Hc, nullptr);
    run_gemm<128, 64, 16, 64, 32, 1, 0, EPI_STORE>(
        attn, Q, AV2, Nc, Zc, Nc, Nc, Dc, Dc,
        (long)Hc * NN, NN, ND, Zc, ND, Zc, Bc * Hc, Hc, nullptr);

    // 5) out = AV1 @ Wq ; out += AV2 @ Wk
    run_gemm<128, 128, 16, 64, 32, 0, 0, EPI_STORE>(
        AV1, Wq, out, Mrows, Dc, Dc, Dc, Dc, Dc, 0, 0, 0, 0, 0, 0, 1, 1, nullptr);
    run_gemm<128, 128, 16, 64, 32, 0, 0, EPI_ADD>(
        AV2, Wk, out, Mrows, Dc, Dc, Dc, Dc, Dc, 0, 0, 0, 0, 0, 0, 1, 1, nullptr);

    // 6) hid = relu(x @ Wmlp^T) ; out += hid @ Wmlp
    run_gemm<128, 128, 16, 64, 32, 0, 1, EPI_RELU>(
        x, Wmlp, hid, Mrows, HIDc, Dc, Dc, Dc, HIDc, 0, 0, 0, 0, 0, 0, 1, 1, nullptr);
    run_gemm<128, 128, 16, 64, 32, 0, 0, EPI_ADD>(
        hid, Wmlp, out, Mrows, Dc, HIDc, HIDc, Dc, Dc, 0, 0, 0, 0, 0, 0, 1, 1, nullptr);
}

// round 3
// speedup vs baseline: 3.9154x; 1.4197x over previous
#include <cuda_runtime.h>
#include <cstdint>

// ---------------------------------------------------------------------------
// KQEnergyBlock: B=8, N=1024, D=768, H=12, Z=64, HID=3072
//   Q = x @ Wq^T ; K = x @ Wk^T
//   S[b,h] = beta_h * Q_h @ K_h^T ; P = softmax(S)
//   AV1 = P @ K_h ; AV2 = P^T @ Q_h
//   out = AV1@Wq + AV2@Wk + relu(x@Wmlp^T)@Wmlp
// tf32 mma.sync.m16n8k8 + cp.async double-buffered pipeline.
// ---------------------------------------------------------------------------

namespace {
constexpr int Bc = 8, Nc = 1024, Dc = 768, Hc = 12, Zc = 64, HIDc = 3072;
constexpr int Mrows = Bc * Nc;  // 8192
}

__device__ float g_Q[Mrows * Dc];
__device__ float g_K[Mrows * Dc];
__device__ float g_AV1[Mrows * Dc];
__device__ float g_AV2[Mrows * Dc];
__device__ float g_attn[(size_t)Bc * Hc * Nc * Nc];   // 402 MB
__device__ float g_hid[(size_t)Mrows * HIDc];         // 100 MB

enum { EPI_STORE = 0, EPI_SCALE = 1, EPI_RELU = 2, EPI_ADD = 3 };

__device__ __forceinline__ uint32_t f2tf32(float f) {
    uint32_t r;
    asm("cvt.rna.tf32.f32 %0, %1;" : "=r"(r) : "f"(f));
    return r;
}

__device__ __forceinline__ void cp_async16(void* smem_dst, const void* gmem_src) {
    uint32_t sa = (uint32_t)__cvta_generic_to_shared(smem_dst);
    asm volatile("cp.async.cg.shared.global [%0], [%1], 16;\n" :: "r"(sa), "l"(gmem_src));
}
__device__ __forceinline__ void cp_commit() {
    asm volatile("cp.async.commit_group;\n");
}
template <int Nw>
__device__ __forceinline__ void cp_wait() {
    asm volatile("cp.async.wait_group %0;\n" :: "n"(Nw));
}

__device__ __forceinline__ void mma_tf32(float c[4],
                                         uint32_t a0, uint32_t a1, uint32_t a2, uint32_t a3,
                                         uint32_t b0, uint32_t b1) {
    asm volatile(
        "mma.sync.aligned.m16n8k8.row.col.f32.tf32.tf32.f32 "
        "{%0,%1,%2,%3}, {%4,%5,%6,%7}, {%8,%9}, {%0,%1,%2,%3};\n"
        : "+f"(c[0]), "+f"(c[1]), "+f"(c[2]), "+f"(c[3])
        : "r"(a0), "r"(a1), "r"(a2), "r"(a3), "r"(b0), "r"(b1));
}

// Batched tf32 tensor-core GEMM, cp.async double-buffered.
//  A logical MxK:  TA=0 -> A[m*lda+k],  TA=1 -> A[k*lda+m]
//  B logical KxN:  TB=0 -> B[k*ldb+n],  TB=1 -> B[n*ldb+k]
// All dims must divide tiles exactly.
template <int BM, int BN, int BK, int WM, int WN, int TA, int TB, int EPI>
__global__ __launch_bounds__((BM / WM) * (BN / WN) * 32)
void gemm_mma(const float* __restrict__ Abase, const float* __restrict__ Bbase,
              float* __restrict__ Cbase,
              int M, int N, int K, int lda, int ldb, int ldc,
              long sAb, long sAh, long sBb, long sBh, long sCb, long sCh,
              int Hdiv, const float* __restrict__ betas)
{
    constexpr int NWARPS = (BM / WM) * (BN / WN);
    constexpr int NT = NWARPS * 32;
    constexpr int MT = WM / 16;
    constexpr int NTI = WN / 8;

    // smem layouts (raw fp32, cp.async friendly, bank-conflict-free pads)
    constexpr int AR = TA ? BK : BM;
    constexpr int AC = TA ? (BM + 8) : (BK + 4);
    constexpr int BR = TB ? BN : BK;
    constexpr int BCc = TB ? (BK + 4) : (BN + 8);

    __shared__ __align__(16) float As[2][AR][AC];
    __shared__ __align__(16) float Bs[2][BR][BCc];

    const int bz = blockIdx.z;
    const int bi = bz / Hdiv;
    const int hi = bz % Hdiv;
    const float* A = Abase + bi * sAb + hi * sAh;
    const float* Bm = Bbase + bi * sBb + hi * sBh;
    float* C = Cbase + bi * sCb + hi * sCh;

    const int t = threadIdx.x;
    const int warp = t >> 5;
    const int lane = t & 31;
    const int group = lane >> 2;   // 0..7
    const int tg = lane & 3;       // 0..3
    const int wm = warp / (BN / WN);
    const int wn = warp % (BN / WN);
    const int m0 = blockIdx.y * BM;
    const int n0 = blockIdx.x * BN;

    const int nk = K / BK;

    // ---- async tile prefetch ----
    auto prefetch = [&](int kt, int s) {
        const int k0 = kt * BK;
        // A tile
        constexpr int ACH = BM * BK / 4;
#pragma unroll
        for (int it = 0; it < ACH / NT; ++it) {
            int c = t + it * NT;
            if (TA == 0) {
                int m = c / (BK / 4), q = c % (BK / 4);
                cp_async16(&As[s][m][q * 4], &A[(long)(m0 + m) * lda + k0 + q * 4]);
            } else {
                int k = c / (BM / 4), mq = c % (BM / 4);
                cp_async16(&As[s][k][mq * 4], &A[(long)(k0 + k) * lda + m0 + mq * 4]);
            }
        }
        // B tile
        constexpr int BCH = BN * BK / 4;
#pragma unroll
        for (int it = 0; it < BCH / NT; ++it) {
            int c = t + it * NT;
            if (TB == 1) {
                int n = c / (BK / 4), q = c % (BK / 4);
                cp_async16(&Bs[s][n][q * 4], &Bm[(long)(n0 + n) * ldb + k0 + q * 4]);
            } else {
                int k = c / (BN / 4), nq = c % (BN / 4);
                cp_async16(&Bs[s][k][nq * 4], &Bm[(long)(k0 + k) * ldb + n0 + nq * 4]);
            }
        }
        cp_commit();
    };

    float acc[MT][NTI][4];
#pragma unroll
    for (int i = 0; i < MT; i++)
#pragma unroll
        for (int j = 0; j < NTI; j++)
#pragma unroll
            for (int r = 0; r < 4; r++) acc[i][j][r] = 0.f;

    prefetch(0, 0);

    for (int kt = 0; kt < nk; kt++) {
        const int s = kt & 1;
        if (kt + 1 < nk) {
            prefetch(kt + 1, s ^ 1);
            cp_wait<1>();
        } else {
            cp_wait<0>();
        }
        __syncthreads();

#pragma unroll
        for (int kk = 0; kk < BK; kk += 8) {
            uint32_t af[MT][4], bf[NTI][2];
#pragma unroll
            for (int mt = 0; mt < MT; mt++) {
                int mr = wm * WM + mt * 16 + group;
                if (TA == 0) {
                    af[mt][0] = f2tf32(As[s][mr][kk + tg]);
                    af[mt][1] = f2tf32(As[s][mr + 8][kk + tg]);
                    af[mt][2] = f2tf32(As[s][mr][kk + tg + 4]);
                    af[mt][3] = f2tf32(As[s][mr + 8][kk + tg + 4]);
                } else {
                    af[mt][0] = f2tf32(As[s][kk + tg][mr]);
                    af[mt][1] = f2tf32(As[s][kk + tg][mr + 8]);
                    af[mt][2] = f2tf32(As[s][kk + tg + 4][mr]);
                    af[mt][3] = f2tf32(As[s][kk + tg + 4][mr + 8]);
                }
            }
#pragma unroll
            for (int nt = 0; nt < NTI; nt++) {
                int nc = wn * WN + nt * 8 + group;
                if (TB == 1) {
                    bf[nt][0] = f2tf32(Bs[s][nc][kk + tg]);
                    bf[nt][1] = f2tf32(Bs[s][nc][kk + tg + 4]);
                } else {
                    bf[nt][0] = f2tf32(Bs[s][kk + tg][nc]);
                    bf[nt][1] = f2tf32(Bs[s][kk + tg + 4][nc]);
                }
            }
#pragma unroll
            for (int mt = 0; mt < MT; mt++)
#pragma unroll
                for (int nt = 0; nt < NTI; nt++)
                    mma_tf32(acc[mt][nt], af[mt][0], af[mt][1], af[mt][2], af[mt][3],
                             bf[nt][0], bf[nt][1]);
        }
        __syncthreads();
    }

    float scale = 1.f;
    if (EPI == EPI_SCALE) scale = betas[hi];

#pragma unroll
    for (int mt = 0; mt < MT; mt++) {
#pragma unroll
        for (int nt = 0; nt < NTI; nt++) {
            int gm = m0 + wm * WM + mt * 16 + group;
            int gn = n0 + wn * WN + nt * 8 + tg * 2;
#pragma unroll
            for (int half = 0; half < 2; half++) {
                int row = gm + half * 8;
                float v0 = acc[mt][nt][half * 2 + 0];
                float v1 = acc[mt][nt][half * 2 + 1];
                if (EPI == EPI_SCALE) { v0 *= scale; v1 *= scale; }
                if (EPI == EPI_RELU)  { v0 = fmaxf(v0, 0.f); v1 = fmaxf(v1, 0.f); }
                float2* p = reinterpret_cast<float2*>(&C[(long)row * ldc + gn]);
                if (EPI == EPI_ADD) {
                    float2 old = *p;
                    p->x = old.x + v0;
                    p->y = old.y + v1;
                } else {
                    float2 w; w.x = v0; w.y = v1;
                    *p = w;
                }
            }
        }
    }
}

// Row softmax over 1024 columns; one 256-thread block per row.
__global__ __launch_bounds__(256) void softmax_k(float* __restrict__ a)
{
    const long row = blockIdx.x;
    float* p = a + row * (long)Nc;
    const int t = threadIdx.x;

    float v[4];
    float m = -1e30f;
#pragma unroll
    for (int i = 0; i < 4; i++) {
        v[i] = p[t + i * 256];
        m = fmaxf(m, v[i]);
    }
    __shared__ float red[256];
    red[t] = m;
    __syncthreads();
#pragma unroll
    for (int s = 128; s > 0; s >>= 1) {
        if (t < s) red[t] = fmaxf(red[t], red[t + s]);
        __syncthreads();
    }
    m = red[0];
    __syncthreads();

    float sum = 0.f;
#pragma unroll
    for (int i = 0; i < 4; i++) {
        v[i] = __expf(v[i] - m);
        sum += v[i];
    }
    red[t] = sum;
    __syncthreads();
#pragma unroll
    for (int s = 128; s > 0; s >>= 1) {
        if (t < s) red[t] += red[t + s];
        __syncthreads();
    }
    const float inv = 1.f / red[0];
#pragma unroll
    for (int i = 0; i < 4; i++) p[t + i * 256] = v[i] * inv;
}

template <int BM, int BN, int BK, int WM, int WN, int TA, int TB, int EPI>
static void run_gemm(const float* A, const float* B, float* C,
                     int M, int N, int K, int lda, int ldb, int ldc,
                     long sAb, long sAh, long sBb, long sBh, long sCb, long sCh,
                     int batches, int Hdiv, const float* betas)
{
    dim3 grid(N / BN, M / BM, batches);
    gemm_mma<BM, BN, BK, WM, WN, TA, TB, EPI>
        <<<grid, (BM / WM) * (BN / WN) * 32>>>(A, B, C, M, N, K, lda, ldb, ldc,
                                               sAb, sAh, sBb, sBh, sCb, sCh,
                                               Hdiv, betas);
}

extern "C" void kernel_launch(void* const* d_in, const int* in_sizes, int n_in,
                              void* d_out, int out_size)
{
    const float* x     = (const float*)d_in[0];
    const float* Wq    = (const float*)d_in[1];
    const float* Wk    = (const float*)d_in[2];
    const float* betas = (const float*)d_in[3];
    const float* Wmlp  = (const float*)d_in[4];
    float* out = (float*)d_out;

    float *Q, *K, *AV1, *AV2, *attn, *hid;
    cudaGetSymbolAddress((void**)&Q,    g_Q);
    cudaGetSymbolAddress((void**)&K,    g_K);
    cudaGetSymbolAddress((void**)&AV1,  g_AV1);
    cudaGetSymbolAddress((void**)&AV2,  g_AV2);
    cudaGetSymbolAddress((void**)&attn, g_attn);
    cudaGetSymbolAddress((void**)&hid,  g_hid);

    const long ND = (long)Nc * Dc;
    const long NN = (long)Nc * Nc;

    // 1) Q = x @ Wq^T ; K = x @ Wk^T
    run_gemm<128, 128, 16, 64, 32, 0, 1, EPI_STORE>(
        x, Wq, Q, Mrows, Dc, Dc, Dc, Dc, Dc, 0, 0, 0, 0, 0, 0, 1, 1, nullptr);
    run_gemm<128, 128, 16, 64, 32, 0, 1, EPI_STORE>(
        x, Wk, K, Mrows, Dc, Dc, Dc, Dc, Dc, 0, 0, 0, 0, 0, 0, 1, 1, nullptr);

    // 2) S[b,h] = beta_h * Q_h @ K_h^T
    run_gemm<128, 128, 16, 64, 32, 0, 1, EPI_SCALE>(
        Q, K, attn, Nc, Nc, Zc, Dc, Dc, Nc,
        ND, Zc, ND, Zc, (long)Hc * NN, NN, Bc * Hc, Hc, betas);

    // 3) row softmax
    softmax_k<<<Bc * Hc * Nc, 256>>>(attn);

    // 4) AV1 = P @ K_h ; AV2 = P^T @ Q_h
    run_gemm<128, 64, 16, 64, 32, 0, 0, EPI_STORE>(
        attn, K, AV1, Nc, Zc, Nc, Nc, Dc, Dc,
        (long)Hc * NN, NN, ND, Zc, ND, Zc, Bc * Hc, Hc, nullptr);
    run_gemm<128, 64, 16, 64, 32, 1, 0, EPI_STORE>(
        attn, Q, AV2, Nc, Zc, Nc, Nc, Dc, Dc,
        (long)Hc * NN, NN, ND, Zc, ND, Zc, Bc * Hc, Hc, nullptr);

    // 5) out = AV1 @ Wq ; out += AV2 @ Wk
    run_gemm<128, 128, 16, 64, 32, 0, 0, EPI_STORE>(
        AV1, Wq, out, Mrows, Dc, Dc, Dc, Dc, Dc, 0, 0, 0, 0, 0, 0, 1, 1, nullptr);
    run_gemm<128, 128, 16, 64, 32, 0, 0, EPI_ADD>(
        AV2, Wk, out, Mrows, Dc, Dc, Dc, Dc, Dc, 0, 0, 0, 0, 0, 0, 1, 1, nullptr);

    // 6) hid = relu(x @ Wmlp^T) ; out += hid @ Wmlp
    run_gemm<128, 128, 16, 64, 32, 0, 1, EPI_RELU>(
        x, Wmlp, hid, Mrows, HIDc, Dc, Dc, Dc, HIDc, 0, 0, 0, 0, 0, 0, 1, 1, nullptr);
    run_gemm<128, 128, 16, 64, 32, 0, 0, EPI_ADD>(
        hid, Wmlp, out, Mrows, Dc, HIDc, HIDc, Dc, Dc, 0, 0, 0, 0, 0, 0, 1, 1, nullptr);
}

// round 4
// speedup vs baseline: 4.3715x; 1.1165x over previous
#include <cuda_runtime.h>
#include <cstdint>

// ---------------------------------------------------------------------------
// KQEnergyBlock: B=8, N=1024, D=768, H=12, Z=64, HID=3072
//   Q = x @ Wq^T ; K = x @ Wk^T
//   Pu[b,h] = exp(beta_h * Q_h @ K_h^T)       (fused into S-GEMM epilogue,
//                                              partial row sums to Zpart)
//   Zinv = 1 / rowsum(Pu)
//   AV1 = diag(Zinv) @ (Pu @ K_h)            (row scale in epilogue)
//   AV2 = Pu^T @ diag(Zinv) @ Q_h            (A-fragment scale in mainloop)
//   out = AV1@Wq + AV2@Wk + relu(x@Wmlp^T)@Wmlp
// tf32 mma.sync.m16n8k8 + 3-stage cp.async pipeline.
// ---------------------------------------------------------------------------

namespace {
constexpr int Bc = 8, Nc = 1024, Dc = 768, Hc = 12, Zc = 64, HIDc = 3072;
constexpr int Mrows = Bc * Nc;  // 8192
}

__device__ float g_Q[Mrows * Dc];
__device__ float g_K[Mrows * Dc];
__device__ float g_AV1[Mrows * Dc];
__device__ float g_AV2[Mrows * Dc];
__device__ float g_attn[(size_t)Bc * Hc * Nc * Nc];   // 402 MB (unnormalized P)
__device__ float g_hid[(size_t)Mrows * HIDc];         // 100 MB
__device__ float g_Zpart[(size_t)Bc * Hc * Nc * 32];  // per-(row, col-block) sums
__device__ float g_Zinv[(size_t)Bc * Hc * Nc];

enum { EPI_STORE = 0, EPI_EXPSUM = 1, EPI_RELU = 2, EPI_ADD = 3, EPI_ROWSCALE = 4 };

__device__ __forceinline__ uint32_t f2tf32(float f) {
    uint32_t r;
    asm("cvt.rna.tf32.f32 %0, %1;" : "=r"(r) : "f"(f));
    return r;
}

__device__ __forceinline__ void cp_async16(void* smem_dst, const void* gmem_src) {
    uint32_t sa = (uint32_t)__cvta_generic_to_shared(smem_dst);
    asm volatile("cp.async.cg.shared.global [%0], [%1], 16;\n" :: "r"(sa), "l"(gmem_src));
}
__device__ __forceinline__ void cp_commit() {
    asm volatile("cp.async.commit_group;\n");
}
template <int Nw>
__device__ __forceinline__ void cp_wait() {
    asm volatile("cp.async.wait_group %0;\n" :: "n"(Nw));
}

__device__ __forceinline__ void mma_tf32(float c[4],
                                         uint32_t a0, uint32_t a1, uint32_t a2, uint32_t a3,
                                         uint32_t b0, uint32_t b1) {
    asm volatile(
        "mma.sync.aligned.m16n8k8.row.col.f32.tf32.tf32.f32 "
        "{%0,%1,%2,%3}, {%4,%5,%6,%7}, {%8,%9}, {%0,%1,%2,%3};\n"
        : "+f"(c[0]), "+f"(c[1]), "+f"(c[2]), "+f"(c[3])
        : "r"(a0), "r"(a1), "r"(a2), "r"(a3), "r"(b0), "r"(b1));
}

// Batched tf32 tensor-core GEMM, 3-stage cp.async pipeline.
//  A logical MxK:  TA=0 -> A[m*lda+k],  TA=1 -> A[k*lda+m]
//  B logical KxN:  TB=0 -> B[k*ldb+n],  TB=1 -> B[n*ldb+k]
//  FIXA=1: multiply A (k-indexed) by aux[bz*saux + k] at fragment load.
//  EPI_EXPSUM: C = exp(beta*acc); write warp-span row sums to aux.
//  EPI_ROWSCALE: C = acc * aux[bz*saux + m].
template <int BM, int BN, int BK, int WM, int WN, int TA, int TB, int EPI, int FIXA>
__global__ __launch_bounds__((BM / WM) * (BN / WN) * 32)
void gemm_mma(const float* __restrict__ Abase, const float* __restrict__ Bbase,
              float* __restrict__ Cbase,
              int M, int N, int K, int lda, int ldb, int ldc,
              long sAb, long sAh, long sBb, long sBh, long sCb, long sCh,
              int Hdiv, const float* __restrict__ betas,
              float* __restrict__ aux, long saux)
{
    constexpr int NWARPS = (BM / WM) * (BN / WN);
    constexpr int NT = NWARPS * 32;
    constexpr int MT = WM / 16;
    constexpr int NTI = WN / 8;
    constexpr int NST = 3;

    constexpr int AR = TA ? BK : BM;
    constexpr int AC = TA ? (BM + 8) : (BK + 4);
    constexpr int BR = TB ? BN : BK;
    constexpr int BCc = TB ? (BK + 4) : (BN + 8);

    __shared__ __align__(16) float As[NST][AR][AC];
    __shared__ __align__(16) float Bs[NST][BR][BCc];

    const int bz = blockIdx.z;
    const int bi = bz / Hdiv;
    const int hi = bz % Hdiv;
    const float* A = Abase + bi * sAb + hi * sAh;
    const float* Bm = Bbase + bi * sBb + hi * sBh;
    float* C = Cbase + bi * sCb + hi * sCh;
    const long auxoff = (long)bz * saux;

    const int t = threadIdx.x;
    const int warp = t >> 5;
    const int lane = t & 31;
    const int group = lane >> 2;
    const int tg = lane & 3;
    const int wm = warp / (BN / WN);
    const int wn = warp % (BN / WN);
    const int m0 = blockIdx.y * BM;
    const int n0 = blockIdx.x * BN;

    const int nk = K / BK;

    auto prefetch = [&](int kt, int s) {
        const int k0 = kt * BK;
        constexpr int ACH = BM * BK / 4;
#pragma unroll
        for (int it = 0; it < ACH / NT; ++it) {
            int c = t + it * NT;
            if (TA == 0) {
                int m = c / (BK / 4), q = c % (BK / 4);
                cp_async16(&As[s][m][q * 4], &A[(long)(m0 + m) * lda + k0 + q * 4]);
            } else {
                int k = c / (BM / 4), mq = c % (BM / 4);
                cp_async16(&As[s][k][mq * 4], &A[(long)(k0 + k) * lda + m0 + mq * 4]);
            }
        }
        constexpr int BCH = BN * BK / 4;
#pragma unroll
        for (int it = 0; it < BCH / NT; ++it) {
            int c = t + it * NT;
            if (TB == 1) {
                int n = c / (BK / 4), q = c % (BK / 4);
                cp_async16(&Bs[s][n][q * 4], &Bm[(long)(n0 + n) * ldb + k0 + q * 4]);
            } else {
                int k = c / (BN / 4), nq = c % (BN / 4);
                cp_async16(&Bs[s][k][nq * 4], &Bm[(long)(k0 + k) * ldb + n0 + nq * 4]);
            }
        }
        cp_commit();
    };

    float acc[MT][NTI][4];
#pragma unroll
    for (int i = 0; i < MT; i++)
#pragma unroll
        for (int j = 0; j < NTI; j++)
#pragma unroll
            for (int r = 0; r < 4; r++) acc[i][j][r] = 0.f;

    prefetch(0, 0);
    if (nk > 1) prefetch(1, 1); else cp_commit();

    for (int kt = 0; kt < nk; kt++) {
        const int s = kt % NST;
        if (kt + 2 < nk) prefetch(kt + 2, (kt + 2) % NST);
        else cp_commit();
        cp_wait<2>();
        __syncthreads();
        const int k0 = kt * BK;

#pragma unroll
        for (int kk = 0; kk < BK; kk += 8) {
            uint32_t af[MT][4], bf[NTI][2];
            float z0 = 1.f, z1 = 1.f;
            if (FIXA) {
                z0 = aux[auxoff + k0 + kk + tg];
                z1 = aux[auxoff + k0 + kk + tg + 4];
            }
#pragma unroll
            for (int mt = 0; mt < MT; mt++) {
                int mr = wm * WM + mt * 16 + group;
                if (TA == 0) {
                    af[mt][0] = f2tf32(As[s][mr][kk + tg]);
                    af[mt][1] = f2tf32(As[s][mr + 8][kk + tg]);
                    af[mt][2] = f2tf32(As[s][mr][kk + tg + 4]);
                    af[mt][3] = f2tf32(As[s][mr + 8][kk + tg + 4]);
                } else {
                    if (FIXA) {
                        af[mt][0] = f2tf32(As[s][kk + tg][mr] * z0);
                        af[mt][1] = f2tf32(As[s][kk + tg][mr + 8] * z0);
                        af[mt][2] = f2tf32(As[s][kk + tg + 4][mr] * z1);
                        af[mt][3] = f2tf32(As[s][kk + tg + 4][mr + 8] * z1);
                    } else {
                        af[mt][0] = f2tf32(As[s][kk + tg][mr]);
                        af[mt][1] = f2tf32(As[s][kk + tg][mr + 8]);
                        af[mt][2] = f2tf32(As[s][kk + tg + 4][mr]);
                        af[mt][3] = f2tf32(As[s][kk + tg + 4][mr + 8]);
                    }
                }
            }
#pragma unroll
            for (int nt = 0; nt < NTI; nt++) {
                int nc = wn * WN + nt * 8 + group;
                if (TB == 1) {
                    bf[nt][0] = f2tf32(Bs[s][nc][kk + tg]);
                    bf[nt][1] = f2tf32(Bs[s][nc][kk + tg + 4]);
                } else {
                    bf[nt][0] = f2tf32(Bs[s][kk + tg][nc]);
                    bf[nt][1] = f2tf32(Bs[s][kk + tg + 4][nc]);
                }
            }
#pragma unroll
            for (int mt = 0; mt < MT; mt++)
#pragma unroll
                for (int nt = 0; nt < NTI; nt++)
                    mma_tf32(acc[mt][nt], af[mt][0], af[mt][1], af[mt][2], af[mt][3],
                             bf[nt][0], bf[nt][1]);
        }
        __syncthreads();
    }

    // ------------- epilogue -------------
    if (EPI == EPI_EXPSUM) {
        const float scale = betas[hi];
        const int nslot = N / WN;
#pragma unroll
        for (int mt = 0; mt < MT; mt++) {
#pragma unroll
            for (int half = 0; half < 2; half++) {
                float rsum = 0.f;
#pragma unroll
                for (int nt = 0; nt < NTI; nt++) {
                    int gm = m0 + wm * WM + mt * 16 + half * 8 + group;
                    int gn = n0 + wn * WN + nt * 8 + tg * 2;
                    float v0 = __expf(scale * acc[mt][nt][half * 2 + 0]);
                    float v1 = __expf(scale * acc[mt][nt][half * 2 + 1]);
                    rsum += v0 + v1;
                    float2 w; w.x = v0; w.y = v1;
                    *reinterpret_cast<float2*>(&C[(long)gm * ldc + gn]) = w;
                }
                rsum += __shfl_xor_sync(0xffffffffu, rsum, 1);
                rsum += __shfl_xor_sync(0xffffffffu, rsum, 2);
                if (tg == 0) {
                    int row = m0 + wm * WM + mt * 16 + half * 8 + group;
                    int slot = n0 / WN + wn;
                    aux[auxoff + (long)row * nslot + slot] = rsum;
                }
            }
        }
        return;
    }

#pragma unroll
    for (int mt = 0; mt < MT; mt++) {
#pragma unroll
        for (int nt = 0; nt < NTI; nt++) {
            int gm = m0 + wm * WM + mt * 16 + group;
            int gn = n0 + wn * WN + nt * 8 + tg * 2;
#pragma unroll
            for (int half = 0; half < 2; half++) {
                int row = gm + half * 8;
                float v0 = acc[mt][nt][half * 2 + 0];
                float v1 = acc[mt][nt][half * 2 + 1];
                if (EPI == EPI_ROWSCALE) {
                    float zi = aux[auxoff + row];
                    v0 *= zi; v1 *= zi;
                }
                if (EPI == EPI_RELU) { v0 = fmaxf(v0, 0.f); v1 = fmaxf(v1, 0.f); }
                float2* p = reinterpret_cast<float2*>(&C[(long)row * ldc + gn]);
                if (EPI == EPI_ADD) {
                    float2 old = *p;
                    p->x = old.x + v0;
                    p->y = old.y + v1;
                } else {
                    float2 w; w.x = v0; w.y = v1;
                    *p = w;
                }
            }
        }
    }
}

// Combine 32 partial sums per row -> reciprocal.
__global__ __launch_bounds__(256) void zcombine_k(const float* __restrict__ part,
                                                  float* __restrict__ zinv)
{
    long i = (long)blockIdx.x * 256 + threadIdx.x;   // one per row, 96*1024 rows
    const float4* p = reinterpret_cast<const float4*>(part + i * 32);
    float s = 0.f;
#pragma unroll
    for (int j = 0; j < 8; j++) {
        float4 v = p[j];
        s += v.x + v.y + v.z + v.w;
    }
    zinv[i] = 1.f / s;
}

template <int BM, int BN, int BK, int WM, int WN, int TA, int TB, int EPI, int FIXA = 0>
static void run_gemm(const float* A, const float* B, float* C,
                     int M, int N, int K, int lda, int ldb, int ldc,
                     long sAb, long sAh, long sBb, long sBh, long sCb, long sCh,
                     int batches, int Hdiv, const float* betas,
                     float* aux = nullptr, long saux = 0)
{
    dim3 grid(N / BN, M / BM, batches);
    gemm_mma<BM, BN, BK, WM, WN, TA, TB, EPI, FIXA>
        <<<grid, (BM / WM) * (BN / WN) * 32>>>(A, B, C, M, N, K, lda, ldb, ldc,
                                               sAb, sAh, sBb, sBh, sCb, sCh,
                                               Hdiv, betas, aux, saux);
}

extern "C" void kernel_launch(void* const* d_in, const int* in_sizes, int n_in,
                              void* d_out, int out_size)
{
    const float* x     = (const float*)d_in[0];
    const float* Wq    = (const float*)d_in[1];
    const float* Wk    = (const float*)d_in[2];
    const float* betas = (const float*)d_in[3];
    const float* Wmlp  = (const float*)d_in[4];
    float* out = (float*)d_out;

    float *Q, *K, *AV1, *AV2, *attn, *hid, *Zpart, *Zinv;
    cudaGetSymbolAddress((void**)&Q,     g_Q);
    cudaGetSymbolAddress((void**)&K,     g_K);
    cudaGetSymbolAddress((void**)&AV1,   g_AV1);
    cudaGetSymbolAddress((void**)&AV2,   g_AV2);
    cudaGetSymbolAddress((void**)&attn,  g_attn);
    cudaGetSymbolAddress((void**)&hid,   g_hid);
    cudaGetSymbolAddress((void**)&Zpart, g_Zpart);
    cudaGetSymbolAddress((void**)&Zinv,  g_Zinv);

    const long ND = (long)Nc * Dc;
    const long NN = (long)Nc * Nc;

    // 1) Q = x @ Wq^T ; K = x @ Wk^T
    run_gemm<128, 128, 16, 64, 32, 0, 1, EPI_STORE>(
        x, Wq, Q, Mrows, Dc, Dc, Dc, Dc, Dc, 0, 0, 0, 0, 0, 0, 1, 1, nullptr);
    run_gemm<128, 128, 16, 64, 32, 0, 1, EPI_STORE>(
        x, Wk, K, Mrows, Dc, Dc, Dc, Dc, Dc, 0, 0, 0, 0, 0, 0, 1, 1, nullptr);

    // 2) Pu = exp(beta * Q@K^T), partial row sums -> Zpart
    run_gemm<128, 128, 16, 64, 32, 0, 1, EPI_EXPSUM>(
        Q, K, attn, Nc, Nc, Zc, Dc, Dc, Nc,
        ND, Zc, ND, Zc, (long)Hc * NN, NN, Bc * Hc, Hc, betas,
        Zpart, (long)Nc * 32);

    // 3) Zinv = 1 / rowsum
    zcombine_k<<<(Bc * Hc * Nc) / 256, 256>>>(Zpart, Zinv);

    // 4) AV1 = diag(Zinv) (Pu @ K_h) ; AV2 = Pu^T diag(Zinv) Q_h
    run_gemm<128, 64, 16, 64, 32, 0, 0, EPI_ROWSCALE>(
        attn, K, AV1, Nc, Zc, Nc, Nc, Dc, Dc,
        (long)Hc * NN, NN, ND, Zc, ND, Zc, Bc * Hc, Hc, nullptr,
        Zinv, (long)Nc);
    run_gemm<128, 64, 16, 64, 32, 1, 0, EPI_STORE, 1>(
        attn, Q, AV2, Nc, Zc, Nc, Nc, Dc, Dc,
        (long)Hc * NN, NN, ND, Zc, ND, Zc, Bc * Hc, Hc, nullptr,
        Zinv, (long)Nc);

    // 5) out = AV1 @ Wq ; out += AV2 @ Wk
    run_gemm<128, 128, 16, 64, 32, 0, 0, EPI_STORE>(
        AV1, Wq, out, Mrows, Dc, Dc, Dc, Dc, Dc, 0, 0, 0, 0, 0, 0, 1, 1, nullptr);
    run_gemm<128, 128, 16, 64, 32, 0, 0, EPI_ADD>(
        AV2, Wk, out, Mrows, Dc, Dc, Dc, Dc, Dc, 0, 0, 0, 0, 0, 0, 1, 1, nullptr);

    // 6) hid = relu(x @ Wmlp^T) ; out += hid @ Wmlp
    run_gemm<128, 128, 16, 64, 32, 0, 1, EPI_RELU>(
        x, Wmlp, hid, Mrows, HIDc, Dc, Dc, Dc, HIDc, 0, 0, 0, 0, 0, 0, 1, 1, nullptr);
    run_gemm<128, 128, 16, 64, 32, 0, 0, EPI_ADD>(
        hid, Wmlp, out, Mrows, Dc, HIDc, HIDc, Dc, Dc, 0, 0, 0, 0, 0, 0, 1, 1, nullptr);
}